// round 2
// baseline (speedup 1.0000x reference)
#include <cuda_runtime.h>
#include <cuda_bf16.h>
#include <math.h>

// ---------------------------------------------------------------------------
// GPT-2 block, fp32 baseline.
// B=2, S=2048, D=1024, H=16, dh=64, INNER=4096
// ---------------------------------------------------------------------------

#define BATCH   2
#define SEQ     2048
#define DMODEL  1024
#define NHEADS  16
#define HDIM    64
#define INNER   4096
#define ROWS    (BATCH * SEQ)          // 4096
#define EPS     1e-5f

// ------------------------- scratch (static device mem) ---------------------
__device__ float g_x   [ROWS * DMODEL];       // ln1 output
__device__ float g_qkv [ROWS * 3 * DMODEL];   // fused qkv
__device__ float g_attn[ROWS * DMODEL];       // attention output (pre-proj)
__device__ float g_h2  [ROWS * DMODEL];       // attn proj + residual
__device__ float g_y   [ROWS * DMODEL];       // ln2 output
__device__ float g_fc  [ROWS * INNER];        // gelu(fc) output

// ------------------------------- LayerNorm ---------------------------------
__global__ void __launch_bounds__(256) ln_kernel(
    const float* __restrict__ in, const float* __restrict__ gamma,
    const float* __restrict__ beta, float* __restrict__ out)
{
    __shared__ float red[16];
    const int row = blockIdx.x;
    const int tid = threadIdx.x;
    const float* x = in + (size_t)row * DMODEL;

    float4 v = *(const float4*)(x + tid * 4);
    float s = v.x + v.y + v.z + v.w;
    float q = v.x * v.x + v.y * v.y + v.z * v.z + v.w * v.w;
    #pragma unroll
    for (int off = 16; off; off >>= 1) {
        s += __shfl_xor_sync(0xffffffffu, s, off);
        q += __shfl_xor_sync(0xffffffffu, q, off);
    }
    const int w = tid >> 5;
    if ((tid & 31) == 0) { red[w] = s; red[8 + w] = q; }
    __syncthreads();
    float st = 0.f, qt = 0.f;
    #pragma unroll
    for (int i = 0; i < 8; i++) { st += red[i]; qt += red[8 + i]; }

    const float mu  = st * (1.0f / DMODEL);
    const float var = qt * (1.0f / DMODEL) - mu * mu;
    const float inv = rsqrtf(var + EPS);

    float4 g = *(const float4*)(gamma + tid * 4);
    float4 b = *(const float4*)(beta  + tid * 4);
    float4 o;
    o.x = (v.x - mu) * inv * g.x + b.x;
    o.y = (v.y - mu) * inv * g.y + b.y;
    o.z = (v.z - mu) * inv * g.z + b.z;
    o.w = (v.w - mu) * inv * g.w + b.w;
    *(float4*)(out + (size_t)row * DMODEL + tid * 4) = o;
}

// --------------------------------- SGEMM -----------------------------------
// C[M,N] = A[M,K] @ B[K,N] + bias  (+ residual | gelu)
// 128x128 tile, BK=8, 8x8 per thread, 256 threads. All dims % 128 == 0.
#define EPI_BIAS  0
#define EPI_RES   1
#define EPI_GELU  2

__device__ __forceinline__ float gelu_exact(float x) {
    return 0.5f * x * (1.0f + erff(x * 0.70710678118654752f));
}

template <int EPI>
__global__ void __launch_bounds__(256) sgemm_kernel(
    const float* __restrict__ A, const float* __restrict__ Bm,
    const float* __restrict__ bias, const float* __restrict__ res,
    float* __restrict__ C, int M, int N, int K)
{
    __shared__ float As[8][128];
    __shared__ float Bs[8][128];

    const int tid  = threadIdx.x;
    const int brow = blockIdx.y;
    const int bcol = blockIdx.x;
    const int tr   = tid >> 4;       // 0..15
    const int tc   = tid & 15;       // 0..15

    const int arow  = tid >> 1;           // 0..127
    const int ak    = (tid & 1) * 4;      // 0 or 4
    const int bkr   = tid >> 5;           // 0..7
    const int bcol4 = (tid & 31) * 4;     // 0..124

    const float* Aptr = A  + (size_t)(brow * 128 + arow) * K + ak;
    const float* Bptr = Bm + (size_t)bkr * N + bcol * 128 + bcol4;

    float acc[8][8];
    #pragma unroll
    for (int i = 0; i < 8; i++)
        #pragma unroll
        for (int j = 0; j < 8; j++) acc[i][j] = 0.f;

    for (int kt = 0; kt < K; kt += 8) {
        float4 a4 = *(const float4*)(Aptr + kt);
        As[ak + 0][arow] = a4.x;
        As[ak + 1][arow] = a4.y;
        As[ak + 2][arow] = a4.z;
        As[ak + 3][arow] = a4.w;
        float4 b4 = *(const float4*)(Bptr + (size_t)kt * N);
        *(float4*)&Bs[bkr][bcol4] = b4;
        __syncthreads();

        #pragma unroll
        for (int k = 0; k < 8; k++) {
            float4 a0 = *(const float4*)&As[k][tr * 8];
            float4 a1 = *(const float4*)&As[k][tr * 8 + 4];
            float4 b0 = *(const float4*)&Bs[k][tc * 8];
            float4 b1 = *(const float4*)&Bs[k][tc * 8 + 4];
            float a[8] = {a0.x, a0.y, a0.z, a0.w, a1.x, a1.y, a1.z, a1.w};
            float b[8] = {b0.x, b0.y, b0.z, b0.w, b1.x, b1.y, b1.z, b1.w};
            #pragma unroll
            for (int i = 0; i < 8; i++)
                #pragma unroll
                for (int j = 0; j < 8; j++)
                    acc[i][j] = fmaf(a[i], b[j], acc[i][j]);
        }
        __syncthreads();
    }

    // epilogue
    #pragma unroll
    for (int i = 0; i < 8; i++) {
        const size_t row = brow * 128 + tr * 8 + i;
        #pragma unroll
        for (int j = 0; j < 8; j += 4) {
            const size_t col = bcol * 128 + tc * 8 + j;
            float4 bv = *(const float4*)(bias + col);
            float4 o;
            o.x = acc[i][j + 0] + bv.x;
            o.y = acc[i][j + 1] + bv.y;
            o.z = acc[i][j + 2] + bv.z;
            o.w = acc[i][j + 3] + bv.w;
            if (EPI == EPI_RES) {
                float4 rv = *(const float4*)(res + row * N + col);
                o.x += rv.x; o.y += rv.y; o.z += rv.z; o.w += rv.w;
            }
            if (EPI == EPI_GELU) {
                o.x = gelu_exact(o.x); o.y = gelu_exact(o.y);
                o.z = gelu_exact(o.z); o.w = gelu_exact(o.w);
            }
            *(float4*)(C + row * N + col) = o;
        }
    }
}

// ----------------------------- Flash attention ------------------------------
// grid = (SEQ/64, BATCH*NHEADS), 256 threads. 64q x 64k tiles, dh = 64.
// Thread (ty,tx) owns a 4x4 micro-tile of the 64x64 score / output tile.
#define ATTN_SMEM_FLOATS (64 * 64 + 64 * 65 + 64 * 65)   // Qs, Ks(pad), Vs(pad)

__global__ void __launch_bounds__(256) attn_kernel(
    const float* __restrict__ qkv, float* __restrict__ out)
{
    extern __shared__ float sm[];
    float* Qs = sm;               // [64][64]
    float* Ks = Qs + 64 * 64;     // [64][65]
    float* Vs = Ks + 64 * 65;     // [64][65]
    float* Ps = Ks;               // P reuses K's smem

    const int qt = blockIdx.x;
    const int b  = blockIdx.y >> 4;
    const int h  = blockIdx.y & 15;
    const int tid = threadIdx.x;
    const int ty = tid >> 4, tx = tid & 15;

    const size_t rowbase = (size_t)b * SEQ * (3 * DMODEL);
    const float* Qg = qkv + rowbase + (size_t)qt * 64 * (3 * DMODEL) + h * HDIM;

    // load Q tile [64][64]
    for (int idx = tid; idx < 64 * 16; idx += 256) {
        const int r = idx >> 4, c = (idx & 15) << 2;
        float4 v = *(const float4*)(Qg + (size_t)r * (3 * DMODEL) + c);
        float* p = Qs + r * 64 + c;
        p[0] = v.x; p[1] = v.y; p[2] = v.z; p[3] = v.w;
    }

    float m_i[4], l_i[4], o[4][4];
    #pragma unroll
    for (int i = 0; i < 4; i++) {
        m_i[i] = -1e30f; l_i[i] = 0.f;
        #pragma unroll
        for (int j = 0; j < 4; j++) o[i][j] = 0.f;
    }

    for (int jt = 0; jt <= qt; jt++) {
        __syncthreads();   // prior-iter P/V reads (and first-iter Q load) done
        const float* Kg = qkv + rowbase + (size_t)jt * 64 * (3 * DMODEL) + DMODEL + h * HDIM;
        const float* Vg = Kg + DMODEL;
        for (int idx = tid; idx < 64 * 16; idx += 256) {
            const int r = idx >> 4, c = (idx & 15) << 2;
            float4 kv = *(const float4*)(Kg + (size_t)r * (3 * DMODEL) + c);
            float* kp = Ks + r * 65 + c;
            kp[0] = kv.x; kp[1] = kv.y; kp[2] = kv.z; kp[3] = kv.w;
            float4 vv = *(const float4*)(Vg + (size_t)r * (3 * DMODEL) + c);
            float* vp = Vs + r * 65 + c;
            vp[0] = vv.x; vp[1] = vv.y; vp[2] = vv.z; vp[3] = vv.w;
        }
        __syncthreads();

        // S = Q @ K^T
        float s[4][4];
        #pragma unroll
        for (int i = 0; i < 4; i++)
            #pragma unroll
            for (int j = 0; j < 4; j++) s[i][j] = 0.f;
        #pragma unroll 4
        for (int d = 0; d < 64; d++) {
            float a[4], bb[4];
            #pragma unroll
            for (int i = 0; i < 4; i++) a[i]  = Qs[(4 * ty + i) * 64 + d];
            #pragma unroll
            for (int j = 0; j < 4; j++) bb[j] = Ks[(4 * tx + j) * 65 + d];
            #pragma unroll
            for (int i = 0; i < 4; i++)
                #pragma unroll
                for (int j = 0; j < 4; j++)
                    s[i][j] = fmaf(a[i], bb[j], s[i][j]);
        }

        // scale + causal mask
        #pragma unroll
        for (int i = 0; i < 4; i++) {
            const int qrow = qt * 64 + 4 * ty + i;
            #pragma unroll
            for (int j = 0; j < 4; j++) {
                const int kcol = jt * 64 + 4 * tx + j;
                s[i][j] = (kcol <= qrow) ? s[i][j] * 0.125f : -1e30f;
            }
        }

        // online softmax (row spread over 16 lanes: width-16 shuffles)
        #pragma unroll
        for (int i = 0; i < 4; i++) {
            float mx = fmaxf(fmaxf(s[i][0], s[i][1]), fmaxf(s[i][2], s[i][3]));
            #pragma unroll
            for (int off = 8; off; off >>= 1)
                mx = fmaxf(mx, __shfl_xor_sync(0xffffffffu, mx, off, 16));
            const float m_new = fmaxf(m_i[i], mx);
            const float alpha = __expf(m_i[i] - m_new);
            float rsum = 0.f;
            #pragma unroll
            for (int j = 0; j < 4; j++) {
                s[i][j] = __expf(s[i][j] - m_new);
                rsum += s[i][j];
            }
            #pragma unroll
            for (int off = 8; off; off >>= 1)
                rsum += __shfl_xor_sync(0xffffffffu, rsum, off, 16);
            l_i[i] = l_i[i] * alpha + rsum;
            m_i[i] = m_new;
            #pragma unroll
            for (int j = 0; j < 4; j++) o[i][j] *= alpha;
        }

        __syncthreads();   // everyone done reading Ks before overwriting with P
        #pragma unroll
        for (int i = 0; i < 4; i++)
            #pragma unroll
            for (int j = 0; j < 4; j++)
                Ps[(4 * ty + i) * 65 + 4 * tx + j] = s[i][j];
        __syncthreads();

        // O += P @ V
        #pragma unroll 4
        for (int j = 0; j < 64; j++) {
            float p[4], v[4];
            #pragma unroll
            for (int i = 0; i < 4; i++) p[i] = Ps[(4 * ty + i) * 65 + j];
            #pragma unroll
            for (int c = 0; c < 4; c++) v[c] = Vs[j * 65 + 4 * tx + c];
            #pragma unroll
            for (int i = 0; i < 4; i++)
                #pragma unroll
                for (int c = 0; c < 4; c++)
                    o[i][c] = fmaf(p[i], v[c], o[i][c]);
        }
    }

    // write normalized output
    float* Og = out + ((size_t)b * SEQ + (size_t)qt * 64) * DMODEL + h * HDIM;
    #pragma unroll
    for (int i = 0; i < 4; i++) {
        const float inv = 1.0f / l_i[i];
        const int r = 4 * ty + i;
        #pragma unroll
        for (int c = 0; c < 4; c++)
            Og[(size_t)r * DMODEL + 4 * tx + c] = o[i][c] * inv;
    }
}

// ------------------------------- launcher -----------------------------------
extern "C" void kernel_launch(void* const* d_in, const int* in_sizes, int n_in,
                              void* d_out, int out_size)
{
    const float* hidden = (const float*)d_in[0];
    const float* w_qkv  = (const float*)d_in[1];
    const float* b_qkv  = (const float*)d_in[2];
    const float* g1     = (const float*)d_in[3];
    const float* be1    = (const float*)d_in[4];
    const float* w_proj = (const float*)d_in[5];
    const float* b_proj = (const float*)d_in[6];
    const float* g2     = (const float*)d_in[7];
    const float* be2    = (const float*)d_in[8];
    const float* w_fc   = (const float*)d_in[9];
    const float* b_fc   = (const float*)d_in[10];
    const float* w_mlp  = (const float*)d_in[11];
    const float* b_mlp  = (const float*)d_in[12];
    float* out = (float*)d_out;

    float *x, *qkv, *attn, *h2, *y, *fc;
    cudaGetSymbolAddress((void**)&x,    g_x);
    cudaGetSymbolAddress((void**)&qkv,  g_qkv);
    cudaGetSymbolAddress((void**)&attn, g_attn);
    cudaGetSymbolAddress((void**)&h2,   g_h2);
    cudaGetSymbolAddress((void**)&y,    g_y);
    cudaGetSymbolAddress((void**)&fc,   g_fc);

    const int attn_smem = ATTN_SMEM_FLOATS * (int)sizeof(float);  // 49664 B
    cudaFuncSetAttribute(attn_kernel,
                         cudaFuncAttributeMaxDynamicSharedMemorySize, attn_smem);

    // 1. LN1
    ln_kernel<<<ROWS, 256>>>(hidden, g1, be1, x);
    // 2. QKV = x @ w_qkv + b_qkv      [4096,1024]x[1024,3072]
    {
        dim3 grid(3 * DMODEL / 128, ROWS / 128);
        sgemm_kernel<EPI_BIAS><<<grid, 256>>>(x, w_qkv, b_qkv, nullptr, qkv,
                                              ROWS, 3 * DMODEL, DMODEL);
    }
    // 3. attention
    {
        dim3 grid(SEQ / 64, BATCH * NHEADS);
        attn_kernel<<<grid, 256, attn_smem>>>(qkv, attn);
    }
    // 4. h2 = attn @ w_proj + b_proj + hidden
    {
        dim3 grid(DMODEL / 128, ROWS / 128);
        sgemm_kernel<EPI_RES><<<grid, 256>>>(attn, w_proj, b_proj, hidden, h2,
                                             ROWS, DMODEL, DMODEL);
    }
    // 5. LN2
    ln_kernel<<<ROWS, 256>>>(h2, g2, be2, y);
    // 6. fc = gelu(y @ w_fc + b_fc)   [4096,1024]x[1024,4096]
    {
        dim3 grid(INNER / 128, ROWS / 128);
        sgemm_kernel<EPI_GELU><<<grid, 256>>>(y, w_fc, b_fc, nullptr, fc,
                                              ROWS, INNER, DMODEL);
    }
    // 7. out = fc @ w_mlp + b_mlp + h2
    {
        dim3 grid(DMODEL / 128, ROWS / 128);
        sgemm_kernel<EPI_RES><<<grid, 256>>>(fc, w_mlp, b_mlp, h2, out,
                                             ROWS, DMODEL, INNER);
    }
}